// round 14
// baseline (speedup 1.0000x reference)
#include <cuda_runtime.h>
#include <math.h>

#define MAX_NODES 50000
#define NPAD_CAP 51200
#define MAX_EDGES 800000
#define D 64
#define B 64
#define HL 128
#define SCAN_TILE 1024
#define POOL_CHUNK 512
#define CSR_BLOCKS 148
#define GIN_BLOCKS 608
#define GIN_SMEM_FLOATS 10368   // wA4 4096 + wB4 4096 + rows/ts 2048 + 128

// ---------------- scratch (device globals; no allocation) ----------------
__device__ __align__(16) int g_counts[NPAD_CAP];
__device__ __align__(16) int g_offs[NPAD_CAP];
__device__ __align__(16) int g_cursor[NPAD_CAP];
__device__ int g_blocksums[64];
__device__ int g_elist[MAX_EDGES];
__device__ __align__(16) float g_hs[MAX_NODES * D];
__device__ __align__(16) float g_h1[MAX_NODES * D];
__device__ __align__(16) float g_sums[B * D];
__device__ float g_cntb[B];
__device__ volatile unsigned g_gen;
__device__ unsigned g_arrive;

// ---------------- software grid barrier (CSR kernel: 148 resident blocks) ----
__device__ __forceinline__ void gbar() {
    __syncthreads();
    if (threadIdx.x == 0) {
        unsigned gen = g_gen;
        __threadfence();
        if (atomicAdd(&g_arrive, 1u) == gridDim.x - 1) {
            g_arrive = 0;
            __threadfence();
            g_gen = gen + 1;
        } else {
            while (g_gen == gen) __nanosleep(64);
        }
        __threadfence();
    }
    __syncthreads();
}

// ---------------- packed f32x2 helpers ----------------
__device__ __forceinline__ void ffma2(unsigned long long& acc,
                                      unsigned long long a, unsigned long long b) {
    asm("fma.rn.f32x2 %0, %1, %2, %3;" : "=l"(acc) : "l"(a), "l"(b), "l"(acc));
}
__device__ __forceinline__ float f32x2_sum(unsigned long long v) {
    float lo = __uint_as_float((unsigned)(v & 0xffffffffull));
    float hi = __uint_as_float((unsigned)(v >> 32));
    return lo + hi;
}

// ---------------- fused CSR build: count -> scan (blocksums) -> fill ----------------
__global__ void __launch_bounds__(256) csr_kernel(
        const int* __restrict__ ei, int n_edges, int nsb,
        int* __restrict__ counts, int* __restrict__ offs,
        int* __restrict__ cursor, int* __restrict__ blocksums,
        int* __restrict__ elist, float* __restrict__ sums, float* __restrict__ cnt) {
    __shared__ int wsum[8];
    __shared__ int part[2];
    int tid = threadIdx.x, bid = blockIdx.x;
    int gtid = bid * 256 + tid;
    int gthreads = gridDim.x * 256;
    int lane = tid & 31, warp = tid >> 5;

    // ---- P0: degree count (+ zero pool accumulators from block 0) ----
    if (bid == 0) {
        for (int i = tid; i < B * D; i += 256) sums[i] = 0.f;
        if (tid < B) cnt[tid] = 0.f;
    }
    int nchunks = (n_edges + 3) >> 2;
    for (int c = gtid; c < nchunks; c += gthreads) {
        int e0 = c * 4;
        if (e0 + 3 < n_edges) {
            int4 d = *(const int4*)(ei + n_edges + e0);
            atomicAdd(&counts[d.x], 1);
            atomicAdd(&counts[d.y], 1);
            atomicAdd(&counts[d.z], 1);
            atomicAdd(&counts[d.w], 1);
        } else {
            for (int e = e0; e < n_edges; e++)
                atomicAdd(&counts[__ldg(ei + n_edges + e)], 1);
        }
    }
    gbar();

    // ---- P1a: per-tile local exclusive scan + tile sum ----
    int4 v; int incl = 0, s = 0;
    if (bid < nsb) {
        int idx = bid * SCAN_TILE + tid * 4;
        v = *(const int4*)(counts + idx);
        s = v.x + v.y + v.z + v.w;
        incl = s;
#pragma unroll
        for (int off = 1; off < 32; off <<= 1) {
            int u = __shfl_up_sync(0xffffffffu, incl, off);
            if (lane >= off) incl += u;
        }
        if (lane == 31) wsum[warp] = incl;
        __syncthreads();
        if (warp == 0) {
            int ws = (lane < 8) ? wsum[lane] : 0;
#pragma unroll
            for (int off = 1; off < 8; off <<= 1) {
                int u = __shfl_up_sync(0xffffffffu, ws, off);
                if (lane >= off) ws += u;
            }
            if (lane < 8) wsum[lane] = ws;
        }
        __syncthreads();
        if (tid == 255) blocksums[bid] = wsum[7];
    }
    gbar();

    // ---- P1b: add base = sum of preceding tile sums; write offs + cursor ----
    if (bid < nsb) {
        int bv = (tid < bid) ? __ldg(blocksums + tid) : 0;   // nsb <= 64
        if (tid < 64) {
#pragma unroll
            for (int off = 16; off; off >>= 1)
                bv += __shfl_down_sync(0xffffffffu, bv, off);
            if (lane == 0) part[warp] = bv;
        }
        __syncthreads();
        int base = part[0] + part[1];
        int wbase = warp ? wsum[warp - 1] : 0;
        int ebase = base + wbase + incl - s;
        int idx = bid * SCAN_TILE + tid * 4;
        int4 e;
        e.x = ebase; e.y = ebase + v.x; e.z = e.y + v.y; e.w = e.z + v.z;
        *(int4*)(offs + idx) = e;
        *(int4*)(cursor + idx) = e;
    }
    gbar();

    // ---- P2: fill edge list (sorted by dst), 4 edges per chunk ----
    for (int c = gtid; c < nchunks; c += gthreads) {
        int e0 = c * 4;
        if (e0 + 3 < n_edges) {
            int4 sr = *(const int4*)(ei + e0);
            int4 d = *(const int4*)(ei + n_edges + e0);
            int p0 = atomicAdd(&cursor[d.x], 1);
            int p1 = atomicAdd(&cursor[d.y], 1);
            int p2 = atomicAdd(&cursor[d.z], 1);
            int p3 = atomicAdd(&cursor[d.w], 1);
            elist[p0] = sr.x;
            elist[p1] = sr.y;
            elist[p2] = sr.z;
            elist[p3] = sr.w;
        } else {
            for (int e = e0; e < n_edges; e++) {
                int sr = __ldg(ei + e);
                int d = __ldg(ei + n_edges + e);
                int p = atomicAdd(&cursor[d], 1);
                elist[p] = sr;
            }
        }
    }
}

// ---------------- CSR gather: outh[i] = x[i] + sum_{j in N(i)} feat[j] ----
// ILP-4 (measured optimum).
__global__ void __launch_bounds__(256) gather_kernel(
        const float* __restrict__ feat, const float* __restrict__ xin,
        const int* __restrict__ elist, const int* __restrict__ offs,
        const int* __restrict__ counts, float* __restrict__ outh, int n) {
    int w = (blockIdx.x * blockDim.x + threadIdx.x) >> 5;
    int lane = threadIdx.x & 31;
    if (w >= n) return;
    int start = __ldg(offs + w);
    int deg = __ldg(counts + w);
    float2 a0 = ((const float2*)(xin + (size_t)w * 64))[lane];
    float2 a1 = make_float2(0.f, 0.f);
    float2 a2 = make_float2(0.f, 0.f);
    float2 a3 = make_float2(0.f, 0.f);
    int e = 0;
    for (; e + 3 < deg; e += 4) {
        int s0 = __ldg(elist + start + e);
        int s1 = __ldg(elist + start + e + 1);
        int s2 = __ldg(elist + start + e + 2);
        int s3 = __ldg(elist + start + e + 3);
        float2 v0 = ((const float2*)(feat + (size_t)s0 * 64))[lane];
        float2 v1 = ((const float2*)(feat + (size_t)s1 * 64))[lane];
        float2 v2 = ((const float2*)(feat + (size_t)s2 * 64))[lane];
        float2 v3 = ((const float2*)(feat + (size_t)s3 * 64))[lane];
        a0.x += v0.x; a0.y += v0.y;
        a1.x += v1.x; a1.y += v1.y;
        a2.x += v2.x; a2.y += v2.y;
        a3.x += v3.x; a3.y += v3.y;
    }
    for (; e < deg; e++) {
        int s0 = __ldg(elist + start + e);
        float2 v0 = ((const float2*)(feat + (size_t)s0 * 64))[lane];
        a0.x += v0.x; a0.y += v0.y;
    }
    float2 r = make_float2(a0.x + a1.x + a2.x + a3.x,
                           a0.y + a1.y + a2.y + a3.y);
    ((float2*)(outh + (size_t)w * 64))[lane] = r;
}

// ---------------- GIN MLP: 4 rows/warp, 4 blocks/SM, no spills ----------------
__global__ void __launch_bounds__(256, 4) gin_kernel(
        const float* __restrict__ hs,
        const float* __restrict__ wA, const float* __restrict__ bA,
        const float* __restrict__ wB, const float* __restrict__ bB,
        float* __restrict__ out, int n) {
    extern __shared__ float smem[];
    float4* wA4 = (float4*)smem;                 // 1024 float4
    float4* wB4 = (float4*)(smem + 4096);        // 1024 float4
    float* rowsbuf = smem + 8192;                // 8 warps * 256 (reused as ts)
    float* bAs = smem + 10240;
    float* bBs = smem + 10304;

    int tid = threadIdx.x, warp = tid >> 5, lane = tid & 31;
    for (int idx = tid; idx < 1024; idx += 256) {
        int j0 = idx & 31, k = (idx >> 5) * 2;
        wA4[idx] = make_float4(wA[j0 * 64 + k], wA[j0 * 64 + k + 1],
                               wA[(j0 + 32) * 64 + k], wA[(j0 + 32) * 64 + k + 1]);
        wB4[idx] = make_float4(wB[j0 * 64 + k], wB[j0 * 64 + k + 1],
                               wB[(j0 + 32) * 64 + k], wB[(j0 + 32) * 64 + k + 1]);
    }
    if (tid < 64) { bAs[tid] = bA[tid]; bBs[tid] = bB[tid]; }
    __syncthreads();

    float* rows = rowsbuf + warp * 256;
    unsigned rows_a = (unsigned)__cvta_generic_to_shared(rows);
    unsigned wA_a = (unsigned)__cvta_generic_to_shared(wA4);
    unsigned wB_a = (unsigned)__cvta_generic_to_shared(wB4);

    float bAj0 = bAs[lane], bAj1 = bAs[lane + 32];
    float bBj0 = bBs[lane], bBj1 = bBs[lane + 32];

    int ngroups = (n + 3) >> 2;
    for (int g = blockIdx.x * 8 + warp; g < ngroups; g += gridDim.x * 8) {
        int r0 = g * 4;
        int nr = min(4, n - r0);
        // load 4 rows into smem (float4, 2 per lane)
#pragma unroll
        for (int t = 0; t < 2; t++) {
            int idx = lane + 32 * t;        // 0..63 float4 slots
            int r = idx >> 4, c4 = idx & 15;
            float4 v = (r < nr) ? ((const float4*)(hs + (size_t)(r0 + r) * 64))[c4]
                                : make_float4(0.f, 0.f, 0.f, 0.f);
            ((float4*)rows)[idx] = v;
        }
        __syncwarp();

        // ---- phase 1: acc = rows @ wA.T ----
        unsigned long long acc[4][2];
#pragma unroll
        for (int i = 0; i < 4; i++) { acc[i][0] = 0ull; acc[i][1] = 0ull; }
#pragma unroll 4
        for (int k4 = 0; k4 < 16; k4++) {
            unsigned long long w0a, w1a, w0b, w1b;
            asm volatile("ld.shared.v2.u64 {%0,%1}, [%2];"
                         : "=l"(w0a), "=l"(w1a)
                         : "r"(wA_a + ((2 * k4) * 32 + lane) * 16));
            asm volatile("ld.shared.v2.u64 {%0,%1}, [%2];"
                         : "=l"(w0b), "=l"(w1b)
                         : "r"(wA_a + ((2 * k4 + 1) * 32 + lane) * 16));
#pragma unroll
            for (int i = 0; i < 4; i++) {
                unsigned long long h0, h1;
                asm volatile("ld.shared.v2.u64 {%0,%1}, [%2];"
                             : "=l"(h0), "=l"(h1)
                             : "r"(rows_a + i * 256 + k4 * 16));
                ffma2(acc[i][0], h0, w0a);
                ffma2(acc[i][1], h0, w1a);
                ffma2(acc[i][0], h1, w0b);
                ffma2(acc[i][1], h1, w1b);
            }
        }
        __syncwarp();
        // overwrite rows with ts = relu(acc + bA)
#pragma unroll
        for (int i = 0; i < 4; i++) {
            rows[i * 64 + lane] = fmaxf(f32x2_sum(acc[i][0]) + bAj0, 0.f);
            rows[i * 64 + lane + 32] = fmaxf(f32x2_sum(acc[i][1]) + bAj1, 0.f);
        }
        __syncwarp();

        // ---- phase 2: out = relu(ts @ wB.T + bB) ----
#pragma unroll
        for (int i = 0; i < 4; i++) { acc[i][0] = 0ull; acc[i][1] = 0ull; }
#pragma unroll 4
        for (int k4 = 0; k4 < 16; k4++) {
            unsigned long long w0a, w1a, w0b, w1b;
            asm volatile("ld.shared.v2.u64 {%0,%1}, [%2];"
                         : "=l"(w0a), "=l"(w1a)
                         : "r"(wB_a + ((2 * k4) * 32 + lane) * 16));
            asm volatile("ld.shared.v2.u64 {%0,%1}, [%2];"
                         : "=l"(w0b), "=l"(w1b)
                         : "r"(wB_a + ((2 * k4 + 1) * 32 + lane) * 16));
#pragma unroll
            for (int i = 0; i < 4; i++) {
                unsigned long long h0, h1;
                asm volatile("ld.shared.v2.u64 {%0,%1}, [%2];"
                             : "=l"(h0), "=l"(h1)
                             : "r"(rows_a + i * 256 + k4 * 16));
                ffma2(acc[i][0], h0, w0a);
                ffma2(acc[i][1], h0, w1a);
                ffma2(acc[i][0], h1, w0b);
                ffma2(acc[i][1], h1, w1b);
            }
        }
        for (int i = 0; i < nr; i++) {
            out[(size_t)(r0 + i) * 64 + lane] = fmaxf(f32x2_sum(acc[i][0]) + bBj0, 0.f);
            out[(size_t)(r0 + i) * 64 + lane + 32] = fmaxf(f32x2_sum(acc[i][1]) + bBj1, 0.f);
        }
        __syncwarp();
    }
}

// ---------------- mean-pool over sorted batch ----------------
__global__ void pool_kernel(const float* __restrict__ h,
                            const int* __restrict__ batch, int n,
                            float* __restrict__ sums, float* __restrict__ cnt) {
    int d = threadIdx.x;  // 64 threads
    int start = blockIdx.x * POOL_CHUNK;
    if (start >= n) return;
    int end = min(start + POOL_CHUNK, n);
    int cur = __ldg(batch + start);
    float acc = 0.f, c = 0.f;
    for (int r = start; r < end; r++) {
        int b = __ldg(batch + r);
        if (b != cur) {
            atomicAdd(&sums[cur * 64 + d], acc);
            if (d == 0) atomicAdd(&cnt[cur], c);
            acc = 0.f; c = 0.f; cur = b;
        }
        acc += h[(size_t)r * 64 + d];
        c += 1.f;
    }
    atomicAdd(&sums[cur * 64 + d], acc);
    if (d == 0) atomicAdd(&cnt[cur], c);
}

// ---------------- fused gates + LSTM cell + FC + softmax ----------------
__global__ void __launch_bounds__(256) tail_kernel(
        const float* __restrict__ sums, const float* __restrict__ cnt,
        const float* __restrict__ h0, const float* __restrict__ c0,
        const float* __restrict__ w_ih, const float* __restrict__ w_hh,
        const float* __restrict__ b_ih, const float* __restrict__ b_hh,
        const float* __restrict__ fc_w, const float* __restrict__ fc_b,
        float* __restrict__ out) {
    __shared__ float ps[64];
    __shared__ float h0s[128];
    __shared__ float gsm[512];
    __shared__ float h1s[128];
    int b = blockIdx.x;
    int tid = threadIdx.x;
    if (tid < 64) ps[tid] = sums[b * 64 + tid] / fmaxf(cnt[b], 1.f);
    if (tid >= 64 && tid < 192) h0s[tid - 64] = h0[b * 128 + (tid - 64)];
    __syncthreads();
#pragma unroll
    for (int jj = 0; jj < 2; jj++) {
        int j = tid + jj * 256;
        float acc = b_ih[j] + b_hh[j];
        const float4* wi = (const float4*)(w_ih + (size_t)j * 64);
#pragma unroll
        for (int k4 = 0; k4 < 16; k4++) {
            float4 w = __ldg(wi + k4);
            acc += w.x * ps[k4 * 4] + w.y * ps[k4 * 4 + 1]
                 + w.z * ps[k4 * 4 + 2] + w.w * ps[k4 * 4 + 3];
        }
        const float4* wh = (const float4*)(w_hh + (size_t)j * 128);
#pragma unroll
        for (int k4 = 0; k4 < 32; k4++) {
            float4 w = __ldg(wh + k4);
            acc += w.x * h0s[k4 * 4] + w.y * h0s[k4 * 4 + 1]
                 + w.z * h0s[k4 * 4 + 2] + w.w * h0s[k4 * 4 + 3];
        }
        gsm[j] = acc;
    }
    __syncthreads();
    if (tid < 128) {
        float gi = gsm[tid], gf = gsm[128 + tid];
        float gg = gsm[256 + tid], go = gsm[384 + tid];
        float si = 1.f / (1.f + expf(-gi));
        float sf = 1.f / (1.f + expf(-gf));
        float so = 1.f / (1.f + expf(-go));
        float c1 = sf * c0[b * 128 + tid] + si * tanhf(gg);
        float h1v = so * tanhf(c1);
        out[B * 32 + b * 128 + tid] = h1v;
        out[B * 32 + B * 128 + b * 128 + tid] = c1;
        h1s[tid] = h1v;
    }
    __syncthreads();
    if (tid < 32) {
        float acc = fc_b[tid];
        const float4* fw = (const float4*)(fc_w + (size_t)tid * 128);
#pragma unroll
        for (int k4 = 0; k4 < 32; k4++) {
            float4 w = __ldg(fw + k4);
            acc += w.x * h1s[k4 * 4] + w.y * h1s[k4 * 4 + 1]
                 + w.z * h1s[k4 * 4 + 2] + w.w * h1s[k4 * 4 + 3];
        }
        float m = acc;
        for (int off = 16; off; off >>= 1)
            m = fmaxf(m, __shfl_xor_sync(0xffffffffu, m, off));
        float e = expf(acc - m);
        float s = e;
        for (int off = 16; off; off >>= 1)
            s += __shfl_xor_sync(0xffffffffu, s, off);
        out[b * 32 + tid] = e / s;
    }
}

// ---------------- launch ----------------
extern "C" void kernel_launch(void* const* d_in, const int* in_sizes, int n_in,
                              void* d_out, int out_size) {
    const float* x     = (const float*)d_in[0];
    const int*   ei    = (const int*)d_in[1];
    const int*   batch = (const int*)d_in[2];
    const float* w1    = (const float*)d_in[3];
    const float* b1    = (const float*)d_in[4];
    const float* w2    = (const float*)d_in[5];
    const float* b2    = (const float*)d_in[6];
    const float* w3    = (const float*)d_in[7];
    const float* b3    = (const float*)d_in[8];
    const float* w4    = (const float*)d_in[9];
    const float* b4    = (const float*)d_in[10];
    const float* w_ih  = (const float*)d_in[11];
    const float* w_hh  = (const float*)d_in[12];
    const float* b_ih  = (const float*)d_in[13];
    const float* b_hh  = (const float*)d_in[14];
    const float* fc_w  = (const float*)d_in[15];
    const float* fc_b  = (const float*)d_in[16];
    const float* h0    = (const float*)d_in[17];
    const float* c0    = (const float*)d_in[18];
    float* out = (float*)d_out;

    int n_nodes = in_sizes[0] / 64;
    int n_edges = in_sizes[1] / 2;
    int npad = (n_nodes + SCAN_TILE - 1) & ~(SCAN_TILE - 1);
    int nsb = npad / SCAN_TILE;

    int* counts;    cudaGetSymbolAddress((void**)&counts, g_counts);
    int* offs;      cudaGetSymbolAddress((void**)&offs, g_offs);
    int* cursor;    cudaGetSymbolAddress((void**)&cursor, g_cursor);
    int* blocksums; cudaGetSymbolAddress((void**)&blocksums, g_blocksums);
    int* elist;     cudaGetSymbolAddress((void**)&elist, g_elist);
    float* hs;      cudaGetSymbolAddress((void**)&hs, g_hs);
    float* h1;      cudaGetSymbolAddress((void**)&h1, g_h1);
    float* sums;    cudaGetSymbolAddress((void**)&sums, g_sums);
    float* cnt;     cudaGetSymbolAddress((void**)&cnt, g_cntb);

    cudaFuncSetAttribute(gin_kernel, cudaFuncAttributeMaxDynamicSharedMemorySize,
                         GIN_SMEM_FLOATS * 4);

    int gather_blocks = (n_nodes * 32 + 255) / 256;
    int pool_blocks = (n_nodes + POOL_CHUNK - 1) / POOL_CHUNK;

    // ---- CSR build: one fused kernel (count -> scan -> fill) ----
    cudaMemsetAsync(counts, 0, npad * sizeof(int));
    csr_kernel<<<CSR_BLOCKS, 256>>>(ei, n_edges, nsb, counts, offs, cursor,
                                    blocksums, elist, sums, cnt);          // 1

    // ---- layer 1 ----
    gather_kernel<<<gather_blocks, 256>>>(x, x, elist, offs, counts, hs, n_nodes);   // 2
    gin_kernel<<<GIN_BLOCKS, 256, GIN_SMEM_FLOATS * 4>>>(hs, w1, b1, w2, b2, h1, n_nodes); // 3

    // ---- layer 2 (gather2 = profiled 4th launch) ----
    gather_kernel<<<gather_blocks, 256>>>(h1, h1, elist, offs, counts, hs, n_nodes); // 4
    gin_kernel<<<GIN_BLOCKS, 256, GIN_SMEM_FLOATS * 4>>>(hs, w3, b3, w4, b4, h1, n_nodes); // 5

    // ---- pooling ----
    pool_kernel<<<pool_blocks, 64>>>(h1, batch, n_nodes, sums, cnt);       // 6

    // ---- LSTM + FC + softmax ----
    tail_kernel<<<B, 256>>>(sums, cnt, h0, c0, w_ih, w_hh, b_ih, b_hh, fc_w, fc_b, out); // 7
}

// round 15
// speedup vs baseline: 1.0461x; 1.0461x over previous
#include <cuda_runtime.h>
#include <math.h>

#define MAX_NODES 50000
#define NPAD_CAP 51200
#define MAX_EDGES 800000
#define D 64
#define B 64
#define HL 128
#define SCAN_TILE 1024
#define POOL_CHUNK 512
#define CSR_BLOCKS 148
#define GIN_BLOCKS 456
#define GIN_SMEM_FLOATS 16512   // wA4 4096 + wB4 4096 + rows 4096 + ts 4096 + 128

// ---------------- scratch (device globals; no allocation) ----------------
__device__ __align__(16) int g_counts[NPAD_CAP];
__device__ __align__(16) int g_offs[NPAD_CAP];
__device__ __align__(16) int g_cursor[NPAD_CAP];
__device__ int g_blocksums[64];
__device__ int g_elist[MAX_EDGES];
__device__ __align__(16) float g_hs[MAX_NODES * D];
__device__ __align__(16) float g_h1[MAX_NODES * D];
__device__ __align__(16) float g_sums[B * D];
__device__ float g_cntb[B];
__device__ volatile unsigned g_gen;
__device__ unsigned g_arrive;

// ---------------- software grid barrier (CSR kernel: 148 resident blocks) ----
__device__ __forceinline__ void gbar() {
    __syncthreads();
    if (threadIdx.x == 0) {
        unsigned gen = g_gen;
        __threadfence();
        if (atomicAdd(&g_arrive, 1u) == gridDim.x - 1) {
            g_arrive = 0;
            __threadfence();
            g_gen = gen + 1;
        } else {
            while (g_gen == gen) __nanosleep(64);
        }
        __threadfence();
    }
    __syncthreads();
}

// ---------------- packed f32x2 helpers ----------------
__device__ __forceinline__ void ffma2(unsigned long long& acc,
                                      unsigned long long a, unsigned long long b) {
    asm("fma.rn.f32x2 %0, %1, %2, %3;" : "=l"(acc) : "l"(a), "l"(b), "l"(acc));
}
__device__ __forceinline__ float f32x2_sum(unsigned long long v) {
    float lo = __uint_as_float((unsigned)(v & 0xffffffffull));
    float hi = __uint_as_float((unsigned)(v >> 32));
    return lo + hi;
}

// ---------------- fused CSR build: count -> scan (blocksums) -> fill ----------------
__global__ void __launch_bounds__(256) csr_kernel(
        const int* __restrict__ ei, int n_edges, int nsb,
        int* __restrict__ counts, int* __restrict__ offs,
        int* __restrict__ cursor, int* __restrict__ blocksums,
        int* __restrict__ elist, float* __restrict__ sums, float* __restrict__ cnt) {
    __shared__ int wsum[8];
    __shared__ int part[2];
    int tid = threadIdx.x, bid = blockIdx.x;
    int gtid = bid * 256 + tid;
    int gthreads = gridDim.x * 256;
    int lane = tid & 31, warp = tid >> 5;

    // ---- P0: degree count (+ zero pool accumulators from block 0) ----
    if (bid == 0) {
        for (int i = tid; i < B * D; i += 256) sums[i] = 0.f;
        if (tid < B) cnt[tid] = 0.f;
    }
    int nchunks = (n_edges + 3) >> 2;
    for (int c = gtid; c < nchunks; c += gthreads) {
        int e0 = c * 4;
        if (e0 + 3 < n_edges) {
            int4 d = *(const int4*)(ei + n_edges + e0);
            atomicAdd(&counts[d.x], 1);
            atomicAdd(&counts[d.y], 1);
            atomicAdd(&counts[d.z], 1);
            atomicAdd(&counts[d.w], 1);
        } else {
            for (int e = e0; e < n_edges; e++)
                atomicAdd(&counts[__ldg(ei + n_edges + e)], 1);
        }
    }
    gbar();

    // ---- P1a: per-tile local exclusive scan + tile sum ----
    int4 v; int incl = 0, s = 0;
    if (bid < nsb) {
        int idx = bid * SCAN_TILE + tid * 4;
        v = *(const int4*)(counts + idx);
        s = v.x + v.y + v.z + v.w;
        incl = s;
#pragma unroll
        for (int off = 1; off < 32; off <<= 1) {
            int u = __shfl_up_sync(0xffffffffu, incl, off);
            if (lane >= off) incl += u;
        }
        if (lane == 31) wsum[warp] = incl;
        __syncthreads();
        if (warp == 0) {
            int ws = (lane < 8) ? wsum[lane] : 0;
#pragma unroll
            for (int off = 1; off < 8; off <<= 1) {
                int u = __shfl_up_sync(0xffffffffu, ws, off);
                if (lane >= off) ws += u;
            }
            if (lane < 8) wsum[lane] = ws;
        }
        __syncthreads();
        if (tid == 255) blocksums[bid] = wsum[7];
    }
    gbar();

    // ---- P1b: add base = sum of preceding tile sums; write offs + cursor ----
    if (bid < nsb) {
        int bv = (tid < bid) ? __ldg(blocksums + tid) : 0;   // nsb <= 64
        if (tid < 64) {
#pragma unroll
            for (int off = 16; off; off >>= 1)
                bv += __shfl_down_sync(0xffffffffu, bv, off);
            if (lane == 0) part[warp] = bv;
        }
        __syncthreads();
        int base = part[0] + part[1];
        int wbase = warp ? wsum[warp - 1] : 0;
        int ebase = base + wbase + incl - s;
        int idx = bid * SCAN_TILE + tid * 4;
        int4 e;
        e.x = ebase; e.y = ebase + v.x; e.z = e.y + v.y; e.w = e.z + v.z;
        *(int4*)(offs + idx) = e;
        *(int4*)(cursor + idx) = e;
    }
    gbar();

    // ---- P2: fill edge list (sorted by dst), 4 edges per chunk ----
    for (int c = gtid; c < nchunks; c += gthreads) {
        int e0 = c * 4;
        if (e0 + 3 < n_edges) {
            int4 sr = *(const int4*)(ei + e0);
            int4 d = *(const int4*)(ei + n_edges + e0);
            int p0 = atomicAdd(&cursor[d.x], 1);
            int p1 = atomicAdd(&cursor[d.y], 1);
            int p2 = atomicAdd(&cursor[d.z], 1);
            int p3 = atomicAdd(&cursor[d.w], 1);
            elist[p0] = sr.x;
            elist[p1] = sr.y;
            elist[p2] = sr.z;
            elist[p3] = sr.w;
        } else {
            for (int e = e0; e < n_edges; e++) {
                int sr = __ldg(ei + e);
                int d = __ldg(ei + n_edges + e);
                int p = atomicAdd(&cursor[d], 1);
                elist[p] = sr;
            }
        }
    }
}

// ---------------- CSR gather: outh[i] = x[i] + sum_{j in N(i)} feat[j] ----
// ILP-4 (measured optimum).
__global__ void __launch_bounds__(256) gather_kernel(
        const float* __restrict__ feat, const float* __restrict__ xin,
        const int* __restrict__ elist, const int* __restrict__ offs,
        const int* __restrict__ counts, float* __restrict__ outh, int n) {
    int w = (blockIdx.x * blockDim.x + threadIdx.x) >> 5;
    int lane = threadIdx.x & 31;
    if (w >= n) return;
    int start = __ldg(offs + w);
    int deg = __ldg(counts + w);
    float2 a0 = ((const float2*)(xin + (size_t)w * 64))[lane];
    float2 a1 = make_float2(0.f, 0.f);
    float2 a2 = make_float2(0.f, 0.f);
    float2 a3 = make_float2(0.f, 0.f);
    int e = 0;
    for (; e + 3 < deg; e += 4) {
        int s0 = __ldg(elist + start + e);
        int s1 = __ldg(elist + start + e + 1);
        int s2 = __ldg(elist + start + e + 2);
        int s3 = __ldg(elist + start + e + 3);
        float2 v0 = ((const float2*)(feat + (size_t)s0 * 64))[lane];
        float2 v1 = ((const float2*)(feat + (size_t)s1 * 64))[lane];
        float2 v2 = ((const float2*)(feat + (size_t)s2 * 64))[lane];
        float2 v3 = ((const float2*)(feat + (size_t)s3 * 64))[lane];
        a0.x += v0.x; a0.y += v0.y;
        a1.x += v1.x; a1.y += v1.y;
        a2.x += v2.x; a2.y += v2.y;
        a3.x += v3.x; a3.y += v3.y;
    }
    for (; e < deg; e++) {
        int s0 = __ldg(elist + start + e);
        float2 v0 = ((const float2*)(feat + (size_t)s0 * 64))[lane];
        a0.x += v0.x; a0.y += v0.y;
    }
    float2 r = make_float2(a0.x + a1.x + a2.x + a3.x,
                           a0.y + a1.y + a2.y + a3.y);
    ((float2*)(outh + (size_t)w * 64))[lane] = r;
}

// ---------------- GIN MLP: k4-blocked, non-volatile loads (ptxas pipelines) ----
__global__ void __launch_bounds__(256) gin_kernel(
        const float* __restrict__ hs,
        const float* __restrict__ wA, const float* __restrict__ bA,
        const float* __restrict__ wB, const float* __restrict__ bB,
        float* __restrict__ out, int n) {
    extern __shared__ float smem[];
    float4* wA4 = (float4*)smem;
    float4* wB4 = (float4*)(smem + 4096);
    float* rowsbuf = smem + 8192;
    float* tsbuf = smem + 12288;
    float* bAs = smem + 16384;
    float* bBs = smem + 16448;

    int tid = threadIdx.x, warp = tid >> 5, lane = tid & 31;
    for (int idx = tid; idx < 1024; idx += 256) {
        int j0 = idx & 31, k = (idx >> 5) * 2;
        wA4[idx] = make_float4(wA[j0 * 64 + k], wA[j0 * 64 + k + 1],
                               wA[(j0 + 32) * 64 + k], wA[(j0 + 32) * 64 + k + 1]);
        wB4[idx] = make_float4(wB[j0 * 64 + k], wB[j0 * 64 + k + 1],
                               wB[(j0 + 32) * 64 + k], wB[(j0 + 32) * 64 + k + 1]);
    }
    if (tid < 64) { bAs[tid] = bA[tid]; bBs[tid] = bB[tid]; }
    __syncthreads();

    float* rows = rowsbuf + warp * 512;
    float* ts = tsbuf + warp * 512;
    // non-volatile typed shared pointers: ptxas may hoist/pipeline freely
    const ulonglong2* wAp = (const ulonglong2*)wA4;       // [k2*32 + lane]
    const ulonglong2* wBp = (const ulonglong2*)wB4;
    const ulonglong2* rowsp = (const ulonglong2*)rows;    // [i*16 + k4]
    const ulonglong2* tsp = (const ulonglong2*)ts;

    float bAj0 = bAs[lane], bAj1 = bAs[lane + 32];
    float bBj0 = bBs[lane], bBj1 = bBs[lane + 32];

    int ngroups = (n + 7) >> 3;
    for (int g = blockIdx.x * 8 + warp; g < ngroups; g += gridDim.x * 8) {
        int r0 = g * 8;
        int nr = min(8, n - r0);
#pragma unroll
        for (int t = 0; t < 4; t++) {
            int idx = lane + 32 * t;
            int r = idx >> 4, c4 = idx & 15;
            float4 v = (r < nr) ? ((const float4*)(hs + (size_t)(r0 + r) * 64))[c4]
                                : make_float4(0.f, 0.f, 0.f, 0.f);
            ((float4*)rows)[idx] = v;
        }
        __syncwarp();

        // ---- phase 1: acc = rows @ wA.T ----
        unsigned long long acc[8][2];
#pragma unroll
        for (int i = 0; i < 8; i++) { acc[i][0] = 0ull; acc[i][1] = 0ull; }
#pragma unroll 4
        for (int k4 = 0; k4 < 16; k4++) {
            ulonglong2 wa = wAp[(2 * k4) * 32 + lane];      // {w0a, w1a}
            ulonglong2 wb = wAp[(2 * k4 + 1) * 32 + lane];  // {w0b, w1b}
#pragma unroll
            for (int i = 0; i < 8; i++) {
                ulonglong2 h = rowsp[i * 16 + k4];          // {h0, h1}
                ffma2(acc[i][0], h.x, wa.x);
                ffma2(acc[i][1], h.x, wa.y);
                ffma2(acc[i][0], h.y, wb.x);
                ffma2(acc[i][1], h.y, wb.y);
            }
        }
#pragma unroll
        for (int i = 0; i < 8; i++) {
            ts[i * 64 + lane] = fmaxf(f32x2_sum(acc[i][0]) + bAj0, 0.f);
            ts[i * 64 + lane + 32] = fmaxf(f32x2_sum(acc[i][1]) + bAj1, 0.f);
        }
        __syncwarp();

        // ---- phase 2: out = relu(ts @ wB.T + bB) ----
#pragma unroll
        for (int i = 0; i < 8; i++) { acc[i][0] = 0ull; acc[i][1] = 0ull; }
#pragma unroll 4
        for (int k4 = 0; k4 < 16; k4++) {
            ulonglong2 wa = wBp[(2 * k4) * 32 + lane];
            ulonglong2 wb = wBp[(2 * k4 + 1) * 32 + lane];
#pragma unroll
            for (int i = 0; i < 8; i++) {
                ulonglong2 h = tsp[i * 16 + k4];
                ffma2(acc[i][0], h.x, wa.x);
                ffma2(acc[i][1], h.x, wa.y);
                ffma2(acc[i][0], h.y, wb.x);
                ffma2(acc[i][1], h.y, wb.y);
            }
        }
        for (int i = 0; i < nr; i++) {
            out[(size_t)(r0 + i) * 64 + lane] = fmaxf(f32x2_sum(acc[i][0]) + bBj0, 0.f);
            out[(size_t)(r0 + i) * 64 + lane + 32] = fmaxf(f32x2_sum(acc[i][1]) + bBj1, 0.f);
        }
        __syncwarp();
    }
}

// ---------------- mean-pool over sorted batch ----------------
__global__ void pool_kernel(const float* __restrict__ h,
                            const int* __restrict__ batch, int n,
                            float* __restrict__ sums, float* __restrict__ cnt) {
    int d = threadIdx.x;  // 64 threads
    int start = blockIdx.x * POOL_CHUNK;
    if (start >= n) return;
    int end = min(start + POOL_CHUNK, n);
    int cur = __ldg(batch + start);
    float acc = 0.f, c = 0.f;
    for (int r = start; r < end; r++) {
        int b = __ldg(batch + r);
        if (b != cur) {
            atomicAdd(&sums[cur * 64 + d], acc);
            if (d == 0) atomicAdd(&cnt[cur], c);
            acc = 0.f; c = 0.f; cur = b;
        }
        acc += h[(size_t)r * 64 + d];
        c += 1.f;
    }
    atomicAdd(&sums[cur * 64 + d], acc);
    if (d == 0) atomicAdd(&cnt[cur], c);
}

// ---------------- fused gates + LSTM cell + FC + softmax ----------------
__global__ void __launch_bounds__(256) tail_kernel(
        const float* __restrict__ sums, const float* __restrict__ cnt,
        const float* __restrict__ h0, const float* __restrict__ c0,
        const float* __restrict__ w_ih, const float* __restrict__ w_hh,
        const float* __restrict__ b_ih, const float* __restrict__ b_hh,
        const float* __restrict__ fc_w, const float* __restrict__ fc_b,
        float* __restrict__ out) {
    __shared__ float ps[64];
    __shared__ float h0s[128];
    __shared__ float gsm[512];
    __shared__ float h1s[128];
    int b = blockIdx.x;
    int tid = threadIdx.x;
    if (tid < 64) ps[tid] = sums[b * 64 + tid] / fmaxf(cnt[b], 1.f);
    if (tid >= 64 && tid < 192) h0s[tid - 64] = h0[b * 128 + (tid - 64)];
    __syncthreads();
#pragma unroll
    for (int jj = 0; jj < 2; jj++) {
        int j = tid + jj * 256;
        float acc = b_ih[j] + b_hh[j];
        const float4* wi = (const float4*)(w_ih + (size_t)j * 64);
#pragma unroll
        for (int k4 = 0; k4 < 16; k4++) {
            float4 w = __ldg(wi + k4);
            acc += w.x * ps[k4 * 4] + w.y * ps[k4 * 4 + 1]
                 + w.z * ps[k4 * 4 + 2] + w.w * ps[k4 * 4 + 3];
        }
        const float4* wh = (const float4*)(w_hh + (size_t)j * 128);
#pragma unroll
        for (int k4 = 0; k4 < 32; k4++) {
            float4 w = __ldg(wh + k4);
            acc += w.x * h0s[k4 * 4] + w.y * h0s[k4 * 4 + 1]
                 + w.z * h0s[k4 * 4 + 2] + w.w * h0s[k4 * 4 + 3];
        }
        gsm[j] = acc;
    }
    __syncthreads();
    if (tid < 128) {
        float gi = gsm[tid], gf = gsm[128 + tid];
        float gg = gsm[256 + tid], go = gsm[384 + tid];
        float si = 1.f / (1.f + expf(-gi));
        float sf = 1.f / (1.f + expf(-gf));
        float so = 1.f / (1.f + expf(-go));
        float c1 = sf * c0[b * 128 + tid] + si * tanhf(gg);
        float h1v = so * tanhf(c1);
        out[B * 32 + b * 128 + tid] = h1v;
        out[B * 32 + B * 128 + b * 128 + tid] = c1;
        h1s[tid] = h1v;
    }
    __syncthreads();
    if (tid < 32) {
        float acc = fc_b[tid];
        const float4* fw = (const float4*)(fc_w + (size_t)tid * 128);
#pragma unroll
        for (int k4 = 0; k4 < 32; k4++) {
            float4 w = __ldg(fw + k4);
            acc += w.x * h1s[k4 * 4] + w.y * h1s[k4 * 4 + 1]
                 + w.z * h1s[k4 * 4 + 2] + w.w * h1s[k4 * 4 + 3];
        }
        float m = acc;
        for (int off = 16; off; off >>= 1)
            m = fmaxf(m, __shfl_xor_sync(0xffffffffu, m, off));
        float e = expf(acc - m);
        float s = e;
        for (int off = 16; off; off >>= 1)
            s += __shfl_xor_sync(0xffffffffu, s, off);
        out[b * 32 + tid] = e / s;
    }
}

// ---------------- launch ----------------
extern "C" void kernel_launch(void* const* d_in, const int* in_sizes, int n_in,
                              void* d_out, int out_size) {
    const float* x     = (const float*)d_in[0];
    const int*   ei    = (const int*)d_in[1];
    const int*   batch = (const int*)d_in[2];
    const float* w1    = (const float*)d_in[3];
    const float* b1    = (const float*)d_in[4];
    const float* w2    = (const float*)d_in[5];
    const float* b2    = (const float*)d_in[6];
    const float* w3    = (const float*)d_in[7];
    const float* b3    = (const float*)d_in[8];
    const float* w4    = (const float*)d_in[9];
    const float* b4    = (const float*)d_in[10];
    const float* w_ih  = (const float*)d_in[11];
    const float* w_hh  = (const float*)d_in[12];
    const float* b_ih  = (const float*)d_in[13];
    const float* b_hh  = (const float*)d_in[14];
    const float* fc_w  = (const float*)d_in[15];
    const float* fc_b  = (const float*)d_in[16];
    const float* h0    = (const float*)d_in[17];
    const float* c0    = (const float*)d_in[18];
    float* out = (float*)d_out;

    int n_nodes = in_sizes[0] / 64;
    int n_edges = in_sizes[1] / 2;
    int npad = (n_nodes + SCAN_TILE - 1) & ~(SCAN_TILE - 1);
    int nsb = npad / SCAN_TILE;

    int* counts;    cudaGetSymbolAddress((void**)&counts, g_counts);
    int* offs;      cudaGetSymbolAddress((void**)&offs, g_offs);
    int* cursor;    cudaGetSymbolAddress((void**)&cursor, g_cursor);
    int* blocksums; cudaGetSymbolAddress((void**)&blocksums, g_blocksums);
    int* elist;     cudaGetSymbolAddress((void**)&elist, g_elist);
    float* hs;      cudaGetSymbolAddress((void**)&hs, g_hs);
    float* h1;      cudaGetSymbolAddress((void**)&h1, g_h1);
    float* sums;    cudaGetSymbolAddress((void**)&sums, g_sums);
    float* cnt;     cudaGetSymbolAddress((void**)&cnt, g_cntb);

    cudaFuncSetAttribute(gin_kernel, cudaFuncAttributeMaxDynamicSharedMemorySize,
                         GIN_SMEM_FLOATS * 4);

    int gather_blocks = (n_nodes * 32 + 255) / 256;
    int pool_blocks = (n_nodes + POOL_CHUNK - 1) / POOL_CHUNK;

    // ---- CSR build: one fused kernel (count -> scan -> fill) ----
    cudaMemsetAsync(counts, 0, npad * sizeof(int));
    csr_kernel<<<CSR_BLOCKS, 256>>>(ei, n_edges, nsb, counts, offs, cursor,
                                    blocksums, elist, sums, cnt);          // 1

    // ---- layer 1 ----
    gather_kernel<<<gather_blocks, 256>>>(x, x, elist, offs, counts, hs, n_nodes);   // 2
    gin_kernel<<<GIN_BLOCKS, 256, GIN_SMEM_FLOATS * 4>>>(hs, w1, b1, w2, b2, h1, n_nodes); // 3

    // ---- layer 2 (gather2 = profiled 4th launch) ----
    gather_kernel<<<gather_blocks, 256>>>(h1, h1, elist, offs, counts, hs, n_nodes); // 4
    gin_kernel<<<GIN_BLOCKS, 256, GIN_SMEM_FLOATS * 4>>>(hs, w3, b3, w4, b4, h1, n_nodes); // 5

    // ---- pooling ----
    pool_kernel<<<pool_blocks, 64>>>(h1, batch, n_nodes, sums, cnt);       // 6

    // ---- LSTM + FC + softmax ----
    tail_kernel<<<B, 256>>>(sums, cnt, h0, c0, w_ih, w_hh, b_ih, b_hh, fc_w, fc_b, out); // 7
}

// round 17
// speedup vs baseline: 1.0567x; 1.0101x over previous
#include <cuda_runtime.h>
#include <math.h>

#define MAX_NODES 50000
#define NPAD_CAP 51200
#define MAX_EDGES 800000
#define D 64
#define B 64
#define HL 128
#define SCAN_TILE 1024
#define POOL_CHUNK 512
#define CSR_BLOCKS 148
#define GIN_BLOCKS 456
#define GIN_SMEM_FLOATS 16512   // wA4 4096 + wB4 4096 + rows 4096 + ts 4096 + 128

// ---------------- scratch (device globals; no allocation) ----------------
__device__ __align__(16) int g_counts[NPAD_CAP];
__device__ __align__(16) int g_offs[NPAD_CAP];
__device__ __align__(16) int g_cursor[NPAD_CAP];
__device__ int g_blocksums[64];
__device__ int g_elist[MAX_EDGES];
__device__ __align__(16) float g_hs[MAX_NODES * D];
__device__ __align__(16) float g_h1[MAX_NODES * D];
__device__ __align__(16) float g_sums[B * D];
__device__ float g_cntb[B];
__device__ volatile unsigned g_gen;
__device__ unsigned g_arrive;

// ---------------- software grid barrier (CSR kernel: 148 resident blocks) ----
__device__ __forceinline__ void gbar() {
    __syncthreads();
    if (threadIdx.x == 0) {
        unsigned gen = g_gen;
        __threadfence();
        if (atomicAdd(&g_arrive, 1u) == gridDim.x - 1) {
            g_arrive = 0;
            __threadfence();
            g_gen = gen + 1;
        } else {
            while (g_gen == gen) __nanosleep(64);
        }
        __threadfence();
    }
    __syncthreads();
}

// ---------------- packed f32x2 helpers ----------------
__device__ __forceinline__ void ffma2(unsigned long long& acc,
                                      unsigned long long a, unsigned long long b) {
    asm("fma.rn.f32x2 %0, %1, %2, %3;" : "=l"(acc) : "l"(a), "l"(b), "l"(acc));
}
__device__ __forceinline__ float f32x2_sum(unsigned long long v) {
    float lo = __uint_as_float((unsigned)(v & 0xffffffffull));
    float hi = __uint_as_float((unsigned)(v >> 32));
    return lo + hi;
}

// ---------------- fused CSR build: count -> scan (blocksums) -> fill ----------------
__global__ void __launch_bounds__(256) csr_kernel(
        const int* __restrict__ ei, int n_edges, int nsb,
        int* __restrict__ counts, int* __restrict__ offs,
        int* __restrict__ cursor, int* __restrict__ blocksums,
        int* __restrict__ elist, float* __restrict__ sums, float* __restrict__ cnt) {
    __shared__ int wsum[8];
    __shared__ int part[2];
    int tid = threadIdx.x, bid = blockIdx.x;
    int gtid = bid * 256 + tid;
    int gthreads = gridDim.x * 256;
    int lane = tid & 31, warp = tid >> 5;

    // ---- P0: degree count (+ zero pool accumulators from block 0) ----
    if (bid == 0) {
        for (int i = tid; i < B * D; i += 256) sums[i] = 0.f;
        if (tid < B) cnt[tid] = 0.f;
    }
    int nchunks = (n_edges + 3) >> 2;
    for (int c = gtid; c < nchunks; c += gthreads) {
        int e0 = c * 4;
        if (e0 + 3 < n_edges) {
            int4 d = *(const int4*)(ei + n_edges + e0);
            atomicAdd(&counts[d.x], 1);
            atomicAdd(&counts[d.y], 1);
            atomicAdd(&counts[d.z], 1);
            atomicAdd(&counts[d.w], 1);
        } else {
            for (int e = e0; e < n_edges; e++)
                atomicAdd(&counts[__ldg(ei + n_edges + e)], 1);
        }
    }
    gbar();

    // ---- P1a: per-tile local exclusive scan + tile sum ----
    int4 v; int incl = 0, s = 0;
    if (bid < nsb) {
        int idx = bid * SCAN_TILE + tid * 4;
        v = *(const int4*)(counts + idx);
        s = v.x + v.y + v.z + v.w;
        incl = s;
#pragma unroll
        for (int off = 1; off < 32; off <<= 1) {
            int u = __shfl_up_sync(0xffffffffu, incl, off);
            if (lane >= off) incl += u;
        }
        if (lane == 31) wsum[warp] = incl;
        __syncthreads();
        if (warp == 0) {
            int ws = (lane < 8) ? wsum[lane] : 0;
#pragma unroll
            for (int off = 1; off < 8; off <<= 1) {
                int u = __shfl_up_sync(0xffffffffu, ws, off);
                if (lane >= off) ws += u;
            }
            if (lane < 8) wsum[lane] = ws;
        }
        __syncthreads();
        if (tid == 255) blocksums[bid] = wsum[7];
    }
    gbar();

    // ---- P1b: add base = sum of preceding tile sums; write offs + cursor ----
    if (bid < nsb) {
        int bv = (tid < bid) ? __ldg(blocksums + tid) : 0;   // nsb <= 64
        if (tid < 64) {
#pragma unroll
            for (int off = 16; off; off >>= 1)
                bv += __shfl_down_sync(0xffffffffu, bv, off);
            if (lane == 0) part[warp] = bv;
        }
        __syncthreads();
        int base = part[0] + part[1];
        int wbase = warp ? wsum[warp - 1] : 0;
        int ebase = base + wbase + incl - s;
        int idx = bid * SCAN_TILE + tid * 4;
        int4 e;
        e.x = ebase; e.y = ebase + v.x; e.z = e.y + v.y; e.w = e.z + v.z;
        *(int4*)(offs + idx) = e;
        *(int4*)(cursor + idx) = e;
    }
    gbar();

    // ---- P2: fill edge list (sorted by dst), 4 edges per chunk ----
    for (int c = gtid; c < nchunks; c += gthreads) {
        int e0 = c * 4;
        if (e0 + 3 < n_edges) {
            int4 sr = *(const int4*)(ei + e0);
            int4 d = *(const int4*)(ei + n_edges + e0);
            int p0 = atomicAdd(&cursor[d.x], 1);
            int p1 = atomicAdd(&cursor[d.y], 1);
            int p2 = atomicAdd(&cursor[d.z], 1);
            int p3 = atomicAdd(&cursor[d.w], 1);
            elist[p0] = sr.x;
            elist[p1] = sr.y;
            elist[p2] = sr.z;
            elist[p3] = sr.w;
        } else {
            for (int e = e0; e < n_edges; e++) {
                int sr = __ldg(ei + e);
                int d = __ldg(ei + n_edges + e);
                int p = atomicAdd(&cursor[d], 1);
                elist[p] = sr;
            }
        }
    }
}

// ---------------- CSR gather: outh[i] = x[i] + sum_{j in N(i)} feat[j] ----
// ILP-4 (measured optimum).
__global__ void __launch_bounds__(256) gather_kernel(
        const float* __restrict__ feat, const float* __restrict__ xin,
        const int* __restrict__ elist, const int* __restrict__ offs,
        const int* __restrict__ counts, float* __restrict__ outh, int n) {
    int w = (blockIdx.x * blockDim.x + threadIdx.x) >> 5;
    int lane = threadIdx.x & 31;
    if (w >= n) return;
    int start = __ldg(offs + w);
    int deg = __ldg(counts + w);
    float2 a0 = ((const float2*)(xin + (size_t)w * 64))[lane];
    float2 a1 = make_float2(0.f, 0.f);
    float2 a2 = make_float2(0.f, 0.f);
    float2 a3 = make_float2(0.f, 0.f);
    int e = 0;
    for (; e + 3 < deg; e += 4) {
        int s0 = __ldg(elist + start + e);
        int s1 = __ldg(elist + start + e + 1);
        int s2 = __ldg(elist + start + e + 2);
        int s3 = __ldg(elist + start + e + 3);
        float2 v0 = ((const float2*)(feat + (size_t)s0 * 64))[lane];
        float2 v1 = ((const float2*)(feat + (size_t)s1 * 64))[lane];
        float2 v2 = ((const float2*)(feat + (size_t)s2 * 64))[lane];
        float2 v3 = ((const float2*)(feat + (size_t)s3 * 64))[lane];
        a0.x += v0.x; a0.y += v0.y;
        a1.x += v1.x; a1.y += v1.y;
        a2.x += v2.x; a2.y += v2.y;
        a3.x += v3.x; a3.y += v3.y;
    }
    for (; e < deg; e++) {
        int s0 = __ldg(elist + start + e);
        float2 v0 = ((const float2*)(feat + (size_t)s0 * 64))[lane];
        a0.x += v0.x; a0.y += v0.y;
    }
    float2 r = make_float2(a0.x + a1.x + a2.x + a3.x,
                           a0.y + a1.y + a2.y + a3.y);
    ((float2*)(outh + (size_t)w * 64))[lane] = r;
}

// ---------------- GIN MLP: k4-blocked + weight prefetch, unroll 8 ----------------
__global__ void __launch_bounds__(256) gin_kernel(
        const float* __restrict__ hs,
        const float* __restrict__ wA, const float* __restrict__ bA,
        const float* __restrict__ wB, const float* __restrict__ bB,
        float* __restrict__ out, int n) {
    extern __shared__ float smem[];
    float4* wA4 = (float4*)smem;
    float4* wB4 = (float4*)(smem + 4096);
    float* rowsbuf = smem + 8192;
    float* tsbuf = smem + 12288;
    float* bAs = smem + 16384;
    float* bBs = smem + 16448;

    int tid = threadIdx.x, warp = tid >> 5, lane = tid & 31;
    for (int idx = tid; idx < 1024; idx += 256) {
        int j0 = idx & 31, k = (idx >> 5) * 2;
        wA4[idx] = make_float4(wA[j0 * 64 + k], wA[j0 * 64 + k + 1],
                               wA[(j0 + 32) * 64 + k], wA[(j0 + 32) * 64 + k + 1]);
        wB4[idx] = make_float4(wB[j0 * 64 + k], wB[j0 * 64 + k + 1],
                               wB[(j0 + 32) * 64 + k], wB[(j0 + 32) * 64 + k + 1]);
    }
    if (tid < 64) { bAs[tid] = bA[tid]; bBs[tid] = bB[tid]; }
    __syncthreads();

    float* rows = rowsbuf + warp * 512;
    float* ts = tsbuf + warp * 512;
    const ulonglong2* wAp = (const ulonglong2*)wA4;       // [k2*32 + lane]
    const ulonglong2* wBp = (const ulonglong2*)wB4;
    const ulonglong2* rowsp = (const ulonglong2*)rows;    // [i*16 + k4]
    const ulonglong2* tsp = (const ulonglong2*)ts;

    float bAj0 = bAs[lane], bAj1 = bAs[lane + 32];
    float bBj0 = bBs[lane], bBj1 = bBs[lane + 32];

    int ngroups = (n + 7) >> 3;
    for (int g = blockIdx.x * 8 + warp; g < ngroups; g += gridDim.x * 8) {
        int r0 = g * 8;
        int nr = min(8, n - r0);
#pragma unroll
        for (int t = 0; t < 4; t++) {
            int idx = lane + 32 * t;
            int r = idx >> 4, c4 = idx & 15;
            float4 v = (r < nr) ? ((const float4*)(hs + (size_t)(r0 + r) * 64))[c4]
                                : make_float4(0.f, 0.f, 0.f, 0.f);
            ((float4*)rows)[idx] = v;
        }
        __syncwarp();

        // ---- phase 1: acc = rows @ wA.T (weights prefetched 1 iter ahead) ----
        unsigned long long acc[8][2];
#pragma unroll
        for (int i = 0; i < 8; i++) { acc[i][0] = 0ull; acc[i][1] = 0ull; }
        {
            ulonglong2 wa_n = wAp[lane];
            ulonglong2 wb_n = wAp[32 + lane];
#pragma unroll 8
            for (int k4 = 0; k4 < 16; k4++) {
                ulonglong2 wa = wa_n, wb = wb_n;
                if (k4 < 15) {
                    wa_n = wAp[(2 * k4 + 2) * 32 + lane];
                    wb_n = wAp[(2 * k4 + 3) * 32 + lane];
                }
#pragma unroll
                for (int i = 0; i < 8; i++) {
                    ulonglong2 h = rowsp[i * 16 + k4];
                    ffma2(acc[i][0], h.x, wa.x);
                    ffma2(acc[i][1], h.x, wa.y);
                    ffma2(acc[i][0], h.y, wb.x);
                    ffma2(acc[i][1], h.y, wb.y);
                }
            }
        }
#pragma unroll
        for (int i = 0; i < 8; i++) {
            ts[i * 64 + lane] = fmaxf(f32x2_sum(acc[i][0]) + bAj0, 0.f);
            ts[i * 64 + lane + 32] = fmaxf(f32x2_sum(acc[i][1]) + bAj1, 0.f);
        }
        __syncwarp();

        // ---- phase 2: out = relu(ts @ wB.T + bB) ----
#pragma unroll
        for (int i = 0; i < 8; i++) { acc[i][0] = 0ull; acc[i][1] = 0ull; }
        {
            ulonglong2 wa_n = wBp[lane];
            ulonglong2 wb_n = wBp[32 + lane];
#pragma unroll 8
            for (int k4 = 0; k4 < 16; k4++) {
                ulonglong2 wa = wa_n, wb = wb_n;
                if (k4 < 15) {
                    wa_n = wBp[(2 * k4 + 2) * 32 + lane];
                    wb_n = wBp[(2 * k4 + 3) * 32 + lane];
                }
#pragma unroll
                for (int i = 0; i < 8; i++) {
                    ulonglong2 h = tsp[i * 16 + k4];
                    ffma2(acc[i][0], h.x, wa.x);
                    ffma2(acc[i][1], h.x, wa.y);
                    ffma2(acc[i][0], h.y, wb.x);
                    ffma2(acc[i][1], h.y, wb.y);
                }
            }
        }
        for (int i = 0; i < nr; i++) {
            out[(size_t)(r0 + i) * 64 + lane] = fmaxf(f32x2_sum(acc[i][0]) + bBj0, 0.f);
            out[(size_t)(r0 + i) * 64 + lane + 32] = fmaxf(f32x2_sum(acc[i][1]) + bBj1, 0.f);
        }
        __syncwarp();
    }
}

// ---------------- mean-pool over sorted batch ----------------
__global__ void pool_kernel(const float* __restrict__ h,
                            const int* __restrict__ batch, int n,
                            float* __restrict__ sums, float* __restrict__ cnt) {
    int d = threadIdx.x;  // 64 threads
    int start = blockIdx.x * POOL_CHUNK;
    if (start >= n) return;
    int end = min(start + POOL_CHUNK, n);
    int cur = __ldg(batch + start);
    float acc = 0.f, c = 0.f;
    for (int r = start; r < end; r++) {
        int b = __ldg(batch + r);
        if (b != cur) {
            atomicAdd(&sums[cur * 64 + d], acc);
            if (d == 0) atomicAdd(&cnt[cur], c);
            acc = 0.f; c = 0.f; cur = b;
        }
        acc += h[(size_t)r * 64 + d];
        c += 1.f;
    }
    atomicAdd(&sums[cur * 64 + d], acc);
    if (d == 0) atomicAdd(&cnt[cur], c);
}

// ---------------- fused gates + LSTM cell + FC + softmax ----------------
__global__ void __launch_bounds__(256) tail_kernel(
        const float* __restrict__ sums, const float* __restrict__ cnt,
        const float* __restrict__ h0, const float* __restrict__ c0,
        const float* __restrict__ w_ih, const float* __restrict__ w_hh,
        const float* __restrict__ b_ih, const float* __restrict__ b_hh,
        const float* __restrict__ fc_w, const float* __restrict__ fc_b,
        float* __restrict__ out) {
    __shared__ float ps[64];
    __shared__ float h0s[128];
    __shared__ float gsm[512];
    __shared__ float h1s[128];
    int b = blockIdx.x;
    int tid = threadIdx.x;
    if (tid < 64) ps[tid] = sums[b * 64 + tid] / fmaxf(cnt[b], 1.f);
    if (tid >= 64 && tid < 192) h0s[tid - 64] = h0[b * 128 + (tid - 64)];
    __syncthreads();
#pragma unroll
    for (int jj = 0; jj < 2; jj++) {
        int j = tid + jj * 256;
        float acc = b_ih[j] + b_hh[j];
        const float4* wi = (const float4*)(w_ih + (size_t)j * 64);
#pragma unroll
        for (int k4 = 0; k4 < 16; k4++) {
            float4 w = __ldg(wi + k4);
            acc += w.x * ps[k4 * 4] + w.y * ps[k4 * 4 + 1]
                 + w.z * ps[k4 * 4 + 2] + w.w * ps[k4 * 4 + 3];
        }
        const float4* wh = (const float4*)(w_hh + (size_t)j * 128);
#pragma unroll
        for (int k4 = 0; k4 < 32; k4++) {
            float4 w = __ldg(wh + k4);
            acc += w.x * h0s[k4 * 4] + w.y * h0s[k4 * 4 + 1]
                 + w.z * h0s[k4 * 4 + 2] + w.w * h0s[k4 * 4 + 3];
        }
        gsm[j] = acc;
    }
    __syncthreads();
    if (tid < 128) {
        float gi = gsm[tid], gf = gsm[128 + tid];
        float gg = gsm[256 + tid], go = gsm[384 + tid];
        float si = 1.f / (1.f + expf(-gi));
        float sf = 1.f / (1.f + expf(-gf));
        float so = 1.f / (1.f + expf(-go));
        float c1 = sf * c0[b * 128 + tid] + si * tanhf(gg);
        float h1v = so * tanhf(c1);
        out[B * 32 + b * 128 + tid] = h1v;
        out[B * 32 + B * 128 + b * 128 + tid] = c1;
        h1s[tid] = h1v;
    }
    __syncthreads();
    if (tid < 32) {
        float acc = fc_b[tid];
        const float4* fw = (const float4*)(fc_w + (size_t)tid * 128);
#pragma unroll
        for (int k4 = 0; k4 < 32; k4++) {
            float4 w = __ldg(fw + k4);
            acc += w.x * h1s[k4 * 4] + w.y * h1s[k4 * 4 + 1]
                 + w.z * h1s[k4 * 4 + 2] + w.w * h1s[k4 * 4 + 3];
        }
        float m = acc;
        for (int off = 16; off; off >>= 1)
            m = fmaxf(m, __shfl_xor_sync(0xffffffffu, m, off));
        float e = expf(acc - m);
        float s = e;
        for (int off = 16; off; off >>= 1)
            s += __shfl_xor_sync(0xffffffffu, s, off);
        out[b * 32 + tid] = e / s;
    }
}

// ---------------- launch ----------------
extern "C" void kernel_launch(void* const* d_in, const int* in_sizes, int n_in,
                              void* d_out, int out_size) {
    const float* x     = (const float*)d_in[0];
    const int*   ei    = (const int*)d_in[1];
    const int*   batch = (const int*)d_in[2];
    const float* w1    = (const float*)d_in[3];
    const float* b1    = (const float*)d_in[4];
    const float* w2    = (const float*)d_in[5];
    const float* b2    = (const float*)d_in[6];
    const float* w3    = (const float*)d_in[7];
    const float* b3    = (const float*)d_in[8];
    const float* w4    = (const float*)d_in[9];
    const float* b4    = (const float*)d_in[10];
    const float* w_ih  = (const float*)d_in[11];
    const float* w_hh  = (const float*)d_in[12];
    const float* b_ih  = (const float*)d_in[13];
    const float* b_hh  = (const float*)d_in[14];
    const float* fc_w  = (const float*)d_in[15];
    const float* fc_b  = (const float*)d_in[16];
    const float* h0    = (const float*)d_in[17];
    const float* c0    = (const float*)d_in[18];
    float* out = (float*)d_out;

    int n_nodes = in_sizes[0] / 64;
    int n_edges = in_sizes[1] / 2;
    int npad = (n_nodes + SCAN_TILE - 1) & ~(SCAN_TILE - 1);
    int nsb = npad / SCAN_TILE;

    int* counts;    cudaGetSymbolAddress((void**)&counts, g_counts);
    int* offs;      cudaGetSymbolAddress((void**)&offs, g_offs);
    int* cursor;    cudaGetSymbolAddress((void**)&cursor, g_cursor);
    int* blocksums; cudaGetSymbolAddress((void**)&blocksums, g_blocksums);
    int* elist;     cudaGetSymbolAddress((void**)&elist, g_elist);
    float* hs;      cudaGetSymbolAddress((void**)&hs, g_hs);
    float* h1;      cudaGetSymbolAddress((void**)&h1, g_h1);
    float* sums;    cudaGetSymbolAddress((void**)&sums, g_sums);
    float* cnt;     cudaGetSymbolAddress((void**)&cnt, g_cntb);

    cudaFuncSetAttribute(gin_kernel, cudaFuncAttributeMaxDynamicSharedMemorySize,
                         GIN_SMEM_FLOATS * 4);

    int gather_blocks = (n_nodes * 32 + 255) / 256;
    int pool_blocks = (n_nodes + POOL_CHUNK - 1) / POOL_CHUNK;

    // ---- CSR build: one fused kernel (count -> scan -> fill) ----
    cudaMemsetAsync(counts, 0, npad * sizeof(int));
    csr_kernel<<<CSR_BLOCKS, 256>>>(ei, n_edges, nsb, counts, offs, cursor,
                                    blocksums, elist, sums, cnt);          // 1

    // ---- layer 1 ----
    gather_kernel<<<gather_blocks, 256>>>(x, x, elist, offs, counts, hs, n_nodes);   // 2
    gin_kernel<<<GIN_BLOCKS, 256, GIN_SMEM_FLOATS * 4>>>(hs, w1, b1, w2, b2, h1, n_nodes); // 3

    // ---- layer 2 (gather2 = profiled 4th launch) ----
    gather_kernel<<<gather_blocks, 256>>>(h1, h1, elist, offs, counts, hs, n_nodes); // 4
    gin_kernel<<<GIN_BLOCKS, 256, GIN_SMEM_FLOATS * 4>>>(hs, w3, b3, w4, b4, h1, n_nodes); // 5

    // ---- pooling ----
    pool_kernel<<<pool_blocks, 64>>>(h1, batch, n_nodes, sums, cnt);       // 6

    // ---- LSTM + FC + softmax ----
    tail_kernel<<<B, 256>>>(sums, cnt, h0, c0, w_ih, w_hh, b_ih, b_hh, fc_w, fc_b, out); // 7
}